// round 9
// baseline (speedup 1.0000x reference)
#include <cuda_runtime.h>

// Problem dims (compile-time, from reference)
#define BDIM 2
#define CDIM 3
#define DDIM 128
#define HDIM 192
#define WDIM 192

// ---------------------------------------------------------------------------
// X pass (R7 proven config): solve along W (contiguous). Warp-local 32x33
// transpose tiles, 6 chunks of 32 columns; y intermediates round-trip through
// `out` (L2-resident), last chunk kept in registers. No reg cap (76 regs).
// ---------------------------------------------------------------------------
constexpr int XWARPS = 8;
constexpr int XTPB   = XWARPS * 32;

__global__ __launch_bounds__(XTPB) void solve_x_kernel(
    const float* __restrict__ in, float* __restrict__ out,
    const float* __restrict__ a, const float* __restrict__ b,
    const float* __restrict__ c)
{
    __shared__ float tile[XWARPS][32][33];
    __shared__ float s_inva[WDIM], s_b[WDIM], s_c[WDIM];

    const int t    = threadIdx.x;
    const int wid  = t >> 5;
    const int lane = t & 31;

    for (int i = t; i < WDIM; i += XTPB) {
        s_inva[i] = 1.0f / a[i];
        if (i < WDIM - 1) { s_b[i] = b[i]; s_c[i] = c[i]; }
    }
    __syncthreads();

    float (*tl)[33] = tile[wid];
    const int line0 = (blockIdx.x * XWARPS + wid) * 32;
    const int r0 = lane >> 3;
    const int cm = (lane & 7) * 4;

    float carry = 0.0f;
    float yreg[32];

    // forward sweep
    for (int k = 0; k < 6; k++) {
        const int c0 = k * 32;
        #pragma unroll
        for (int rr = 0; rr < 32; rr += 4) {
            const int r = rr + r0;
            float4 v = *(const float4*)(in + (size_t)(line0 + r) * WDIM + c0 + cm);
            tl[r][cm]     = v.x; tl[r][cm + 1] = v.y;
            tl[r][cm + 2] = v.z; tl[r][cm + 3] = v.w;
        }
        __syncwarp();
        #pragma unroll
        for (int j = 0; j < 32; j++) {
            const float x = tl[lane][j];
            const int i = c0 + j;
            carry = (i == 0) ? x : fmaf(-s_c[i - 1], carry, x);
            yreg[j] = carry;
        }
        if (k < 5) {
            #pragma unroll
            for (int j = 0; j < 32; j++) tl[lane][j] = yreg[j];
            __syncwarp();
            #pragma unroll
            for (int rr = 0; rr < 32; rr += 4) {
                const int r = rr + r0;
                float4 v = make_float4(tl[r][cm], tl[r][cm + 1],
                                       tl[r][cm + 2], tl[r][cm + 3]);
                *(float4*)(out + (size_t)(line0 + r) * WDIM + c0 + cm) = v;
            }
        }
        __syncwarp();
    }

    // backward sweep: chunk 5 from registers
    {
        const int c0 = 5 * 32;
        #pragma unroll
        for (int j = 31; j >= 0; j--) {
            const int i = c0 + j;
            const float x = yreg[j];
            carry = (i == WDIM - 1) ? x * s_inva[i]
                                    : fmaf(-s_b[i], carry, x) * s_inva[i];
            yreg[j] = carry;
        }
        #pragma unroll
        for (int j = 0; j < 32; j++) tl[lane][j] = yreg[j];
        __syncwarp();
        #pragma unroll
        for (int rr = 0; rr < 32; rr += 4) {
            const int r = rr + r0;
            float4 v = make_float4(tl[r][cm], tl[r][cm + 1],
                                   tl[r][cm + 2], tl[r][cm + 3]);
            *(float4*)(out + (size_t)(line0 + r) * WDIM + c0 + cm) = v;
        }
        __syncwarp();
    }
    for (int k = 4; k >= 0; k--) {
        const int c0 = k * 32;
        #pragma unroll
        for (int rr = 0; rr < 32; rr += 4) {
            const int r = rr + r0;
            float4 v = *(const float4*)(out + (size_t)(line0 + r) * WDIM + c0 + cm);
            tl[r][cm]     = v.x; tl[r][cm + 1] = v.y;
            tl[r][cm + 2] = v.z; tl[r][cm + 3] = v.w;
        }
        __syncwarp();
        #pragma unroll
        for (int j = 31; j >= 0; j--) {
            const int i = c0 + j;
            carry = fmaf(-s_b[i], carry, tl[lane][j]) * s_inva[i];
            yreg[j] = carry;
        }
        #pragma unroll
        for (int j = 0; j < 32; j++) tl[lane][j] = yreg[j];
        __syncwarp();
        #pragma unroll
        for (int rr = 0; rr < 32; rr += 4) {
            const int r = rr + r0;
            float4 v = make_float4(tl[r][cm], tl[r][cm + 1],
                                   tl[r][cm + 2], tl[r][cm + 3]);
            *(float4*)(out + (size_t)(line0 + r) * WDIM + c0 + cm) = v;
        }
        __syncwarp();
    }
}

// ---------------------------------------------------------------------------
// Y pass: scalar thread-per-line (coalesced across w). Forward y: last
// YHOLD=128 steps in registers, first 64 steps in a SMEM spill buffer
// (never touches global). Global traffic = read x + write z only.
// ---------------------------------------------------------------------------
constexpr int STPB   = 128;
constexpr int YHOLD  = 128;
constexpr int YSPILL = HDIM - YHOLD;   // 64

__global__ __launch_bounds__(STPB, 1) void solve_y_kernel(
    float* __restrict__ data,
    const float* __restrict__ a, const float* __restrict__ b,
    const float* __restrict__ c)
{
    __shared__ float s_inva[HDIM], s_binva[HDIM], s_c[HDIM];
    __shared__ float yspill[YSPILL][STPB];    // 64*128*4 = 32 KB

    const int t = threadIdx.x;
    for (int i = t; i < HDIM; i += STPB) {
        const float iv = 1.0f / a[i];
        s_inva[i]  = iv;
        s_binva[i] = (i < HDIM - 1) ? b[i] * iv : 0.0f;
        s_c[i]     = (i < HDIM - 1) ? c[i] : 0.0f;
    }
    __syncthreads();

    const int L   = blockIdx.x * STPB + t;    // line over (b,c,d) x w
    const int bcd = L / WDIM;
    const int w   = L - bcd * WDIM;
    float* p = data + (size_t)bcd * (HDIM * WDIM) + w;

    float yreg[YHOLD];
    float carry = p[0];
    yspill[0][t] = carry;
    #pragma unroll
    for (int i = 1; i < HDIM; i++) {
        carry = fmaf(-s_c[i - 1], carry, p[(size_t)i * WDIM]);
        if (i < YSPILL) yspill[i][t] = carry;
        else            yreg[i - YSPILL] = carry;
    }

    // backward: register-held region (binva[H-1]==0 unifies the start)
    carry = 0.0f;
    #pragma unroll
    for (int i = HDIM - 1; i >= YSPILL; i--) {
        carry = fmaf(-s_binva[i], carry, yreg[i - YSPILL] * s_inva[i]);
        p[(size_t)i * WDIM] = carry;
    }
    // smem-spilled region (lane-consecutive -> conflict-free LDS)
    #pragma unroll
    for (int i = YSPILL - 1; i >= 0; i--) {
        carry = fmaf(-s_binva[i], carry, yspill[i][t] * s_inva[i]);
        p[(size_t)i * WDIM] = carry;
    }
}

// ---------------------------------------------------------------------------
// Z pass: scalar thread-per-line, y fully register-held (N=128).
// ---------------------------------------------------------------------------
__global__ __launch_bounds__(STPB, 1) void solve_z_kernel(
    float* __restrict__ data,
    const float* __restrict__ a, const float* __restrict__ b,
    const float* __restrict__ c)
{
    __shared__ float s_inva[DDIM], s_binva[DDIM], s_c[DDIM];
    const int t = threadIdx.x;
    for (int i = t; i < DDIM; i += STPB) {
        const float iv = 1.0f / a[i];
        s_inva[i]  = iv;
        s_binva[i] = (i < DDIM - 1) ? b[i] * iv : 0.0f;
        s_c[i]     = (i < DDIM - 1) ? c[i] : 0.0f;
    }
    __syncthreads();

    constexpr int PL = HDIM * WDIM;
    const int L  = blockIdx.x * STPB + t;     // line over (b,c) x (h,w)
    const int bc = L / PL;
    const int hw = L - bc * PL;
    float* p = data + (size_t)bc * (DDIM * PL) + hw;

    float yreg[DDIM];
    float carry = p[0];
    yreg[0] = carry;
    #pragma unroll
    for (int i = 1; i < DDIM; i++) {
        carry = fmaf(-s_c[i - 1], carry, p[(size_t)i * PL]);
        yreg[i] = carry;
    }

    carry = 0.0f;
    #pragma unroll
    for (int i = DDIM - 1; i >= 0; i--) {
        carry = fmaf(-s_binva[i], carry, yreg[i] * s_inva[i]);
        p[(size_t)i * PL] = carry;
    }
}

// ---------------------------------------------------------------------------
// Launch
// ---------------------------------------------------------------------------
extern "C" void kernel_launch(void* const* d_in, const int* in_sizes, int n_in,
                              void* d_out, int out_size)
{
    const float* field = (const float*)d_in[0];
    const float* ax = (const float*)d_in[1];
    const float* bx = (const float*)d_in[2];
    const float* cx = (const float*)d_in[3];
    const float* ay = (const float*)d_in[4];
    const float* by = (const float*)d_in[5];
    const float* cy = (const float*)d_in[6];
    const float* az = (const float*)d_in[7];
    const float* bz = (const float*)d_in[8];
    const float* cz = (const float*)d_in[9];
    float* out = (float*)d_out;

    (void)in_sizes; (void)n_in; (void)out_size;

    // X: 147456 lines / 256 = 576 blocks
    const int lines_x = BDIM * CDIM * DDIM * HDIM;
    solve_x_kernel<<<lines_x / (XWARPS * 32), XTPB>>>(field, out, ax, bx, cx);

    // Y: lines = b*c*d*w = 147456 / 128 = 1152 blocks
    const int lines_y = BDIM * CDIM * DDIM * WDIM;
    solve_y_kernel<<<lines_y / STPB, STPB>>>(out, ay, by, cy);

    // Z: lines = b*c*h*w = 221184 / 128 = 1728 blocks
    const int lines_z = BDIM * CDIM * HDIM * WDIM;
    solve_z_kernel<<<lines_z / STPB, STPB>>>(out, az, bz, cz);
}

// round 10
// speedup vs baseline: 1.0239x; 1.0239x over previous
#include <cuda_runtime.h>

// Problem dims (compile-time, from reference)
#define BDIM 2
#define CDIM 3
#define DDIM 128
#define HDIM 192
#define WDIM 192

// ---------------------------------------------------------------------------
// X pass (R9 measured-best: 59.5us): solve along W (contiguous). Warp-local
// 32x33 transpose tiles, 6 chunks of 32 columns; y intermediates round-trip
// through `out` (L2-resident), last chunk kept in registers. No reg cap.
// ---------------------------------------------------------------------------
constexpr int XWARPS = 8;
constexpr int XTPB   = XWARPS * 32;

__global__ __launch_bounds__(XTPB) void solve_x_kernel(
    const float* __restrict__ in, float* __restrict__ out,
    const float* __restrict__ a, const float* __restrict__ b,
    const float* __restrict__ c)
{
    __shared__ float tile[XWARPS][32][33];
    __shared__ float s_inva[WDIM], s_b[WDIM], s_c[WDIM];

    const int t    = threadIdx.x;
    const int wid  = t >> 5;
    const int lane = t & 31;

    for (int i = t; i < WDIM; i += XTPB) {
        s_inva[i] = 1.0f / a[i];
        if (i < WDIM - 1) { s_b[i] = b[i]; s_c[i] = c[i]; }
    }
    __syncthreads();

    float (*tl)[33] = tile[wid];
    const int line0 = (blockIdx.x * XWARPS + wid) * 32;
    const int r0 = lane >> 3;
    const int cm = (lane & 7) * 4;

    float carry = 0.0f;
    float yreg[32];

    // forward sweep
    for (int k = 0; k < 6; k++) {
        const int c0 = k * 32;
        #pragma unroll
        for (int rr = 0; rr < 32; rr += 4) {
            const int r = rr + r0;
            float4 v = *(const float4*)(in + (size_t)(line0 + r) * WDIM + c0 + cm);
            tl[r][cm]     = v.x; tl[r][cm + 1] = v.y;
            tl[r][cm + 2] = v.z; tl[r][cm + 3] = v.w;
        }
        __syncwarp();
        #pragma unroll
        for (int j = 0; j < 32; j++) {
            const float x = tl[lane][j];
            const int i = c0 + j;
            carry = (i == 0) ? x : fmaf(-s_c[i - 1], carry, x);
            yreg[j] = carry;
        }
        if (k < 5) {
            #pragma unroll
            for (int j = 0; j < 32; j++) tl[lane][j] = yreg[j];
            __syncwarp();
            #pragma unroll
            for (int rr = 0; rr < 32; rr += 4) {
                const int r = rr + r0;
                float4 v = make_float4(tl[r][cm], tl[r][cm + 1],
                                       tl[r][cm + 2], tl[r][cm + 3]);
                *(float4*)(out + (size_t)(line0 + r) * WDIM + c0 + cm) = v;
            }
        }
        __syncwarp();
    }

    // backward sweep: chunk 5 from registers
    {
        const int c0 = 5 * 32;
        #pragma unroll
        for (int j = 31; j >= 0; j--) {
            const int i = c0 + j;
            const float x = yreg[j];
            carry = (i == WDIM - 1) ? x * s_inva[i]
                                    : fmaf(-s_b[i], carry, x) * s_inva[i];
            yreg[j] = carry;
        }
        #pragma unroll
        for (int j = 0; j < 32; j++) tl[lane][j] = yreg[j];
        __syncwarp();
        #pragma unroll
        for (int rr = 0; rr < 32; rr += 4) {
            const int r = rr + r0;
            float4 v = make_float4(tl[r][cm], tl[r][cm + 1],
                                   tl[r][cm + 2], tl[r][cm + 3]);
            *(float4*)(out + (size_t)(line0 + r) * WDIM + c0 + cm) = v;
        }
        __syncwarp();
    }
    for (int k = 4; k >= 0; k--) {
        const int c0 = k * 32;
        #pragma unroll
        for (int rr = 0; rr < 32; rr += 4) {
            const int r = rr + r0;
            float4 v = *(const float4*)(out + (size_t)(line0 + r) * WDIM + c0 + cm);
            tl[r][cm]     = v.x; tl[r][cm + 1] = v.y;
            tl[r][cm + 2] = v.z; tl[r][cm + 3] = v.w;
        }
        __syncwarp();
        #pragma unroll
        for (int j = 31; j >= 0; j--) {
            const int i = c0 + j;
            carry = fmaf(-s_b[i], carry, tl[lane][j]) * s_inva[i];
            yreg[j] = carry;
        }
        #pragma unroll
        for (int j = 0; j < 32; j++) tl[lane][j] = yreg[j];
        __syncwarp();
        #pragma unroll
        for (int rr = 0; rr < 32; rr += 4) {
            const int r = rr + r0;
            float4 v = make_float4(tl[r][cm], tl[r][cm + 1],
                                   tl[r][cm + 2], tl[r][cm + 3]);
            *(float4*)(out + (size_t)(line0 + r) * WDIM + c0 + cm) = v;
        }
        __syncwarp();
    }
}

// ---------------------------------------------------------------------------
// Strided passes (R8 measured-best): scalar thread-per-line (coalesced
// across w), forward y held in REGISTERS for the last HOLD steps; first
// N-HOLD steps round-trip through GLOBAL (write-back to L2, reloads are
// MLP-batched L2 hits). 128-thread blocks.
// ---------------------------------------------------------------------------
template <int N, int HOLD, int STRIDE>
__device__ __forceinline__ void solve_line_reg(
    float* __restrict__ p,
    const float* __restrict__ s_inva,
    const float* __restrict__ s_binva,
    const float* __restrict__ s_c)
{
    constexpr int SPILL = N - HOLD;   // steps whose y round-trips via global
    float yreg[HOLD];
    float carry;

    // forward sweep
    carry = p[0];
    if (SPILL > 0) p[0] = carry; else yreg[0] = carry;
    #pragma unroll
    for (int i = 1; i < N; i++) {
        carry = fmaf(-s_c[i - 1], carry, p[(size_t)i * STRIDE]);
        if (i < SPILL) p[(size_t)i * STRIDE] = carry;
        else           yreg[i - SPILL] = carry;
    }

    // backward sweep: register-held region (binva[N-1]==0 unifies i==N-1)
    carry = 0.0f;
    #pragma unroll
    for (int i = N - 1; i >= SPILL; i--) {
        carry = fmaf(-s_binva[i], carry, yreg[i - SPILL] * s_inva[i]);
        p[(size_t)i * STRIDE] = carry;
    }
    // spilled region: reload y from global (L2-hot)
    #pragma unroll
    for (int i = SPILL - 1; i >= 0; i--) {
        carry = fmaf(-s_binva[i], carry, p[(size_t)i * STRIDE] * s_inva[i]);
        p[(size_t)i * STRIDE] = carry;
    }
}

constexpr int STPB = 128;

template <int N>
__device__ __forceinline__ void load_coeffs_s(
    const float* __restrict__ a, const float* __restrict__ b,
    const float* __restrict__ c,
    float* __restrict__ s_inva, float* __restrict__ s_binva,
    float* __restrict__ s_c)
{
    for (int i = threadIdx.x; i < N; i += STPB) {
        const float iv = 1.0f / a[i];
        s_inva[i]  = iv;
        s_binva[i] = (i < N - 1) ? b[i] * iv : 0.0f;
        s_c[i]     = (i < N - 1) ? c[i] : 0.0f;
    }
}

__global__ __launch_bounds__(STPB, 1) void solve_y_kernel(
    float* __restrict__ data,
    const float* __restrict__ a, const float* __restrict__ b,
    const float* __restrict__ c)
{
    __shared__ float s_inva[HDIM], s_binva[HDIM], s_c[HDIM];
    load_coeffs_s<HDIM>(a, b, c, s_inva, s_binva, s_c);
    __syncthreads();

    const int L   = blockIdx.x * STPB + threadIdx.x;  // line over (b,c,d) x w
    const int bcd = L / WDIM;
    const int w   = L - bcd * WDIM;
    float* p = data + (size_t)bcd * (HDIM * WDIM) + w;
    solve_line_reg<HDIM, 128, WDIM>(p, s_inva, s_binva, s_c);
}

__global__ __launch_bounds__(STPB, 1) void solve_z_kernel(
    float* __restrict__ data,
    const float* __restrict__ a, const float* __restrict__ b,
    const float* __restrict__ c)
{
    __shared__ float s_inva[DDIM], s_binva[DDIM], s_c[DDIM];
    load_coeffs_s<DDIM>(a, b, c, s_inva, s_binva, s_c);
    __syncthreads();

    const int L  = blockIdx.x * STPB + threadIdx.x;   // line over (b,c) x (h,w)
    const int bc = L / (HDIM * WDIM);
    const int hw = L - bc * (HDIM * WDIM);
    float* p = data + (size_t)bc * (DDIM * HDIM * WDIM) + hw;
    solve_line_reg<DDIM, DDIM, HDIM * WDIM>(p, s_inva, s_binva, s_c);
}

// ---------------------------------------------------------------------------
// Launch
// ---------------------------------------------------------------------------
extern "C" void kernel_launch(void* const* d_in, const int* in_sizes, int n_in,
                              void* d_out, int out_size)
{
    const float* field = (const float*)d_in[0];
    const float* ax = (const float*)d_in[1];
    const float* bx = (const float*)d_in[2];
    const float* cx = (const float*)d_in[3];
    const float* ay = (const float*)d_in[4];
    const float* by = (const float*)d_in[5];
    const float* cy = (const float*)d_in[6];
    const float* az = (const float*)d_in[7];
    const float* bz = (const float*)d_in[8];
    const float* cz = (const float*)d_in[9];
    float* out = (float*)d_out;

    (void)in_sizes; (void)n_in; (void)out_size;

    // X: 147456 lines / 256 = 576 blocks
    const int lines_x = BDIM * CDIM * DDIM * HDIM;
    solve_x_kernel<<<lines_x / (XWARPS * 32), XTPB>>>(field, out, ax, bx, cx);

    // Y: lines = b*c*d*w = 147456 / 128 = 1152 blocks
    const int lines_y = BDIM * CDIM * DDIM * WDIM;
    solve_y_kernel<<<lines_y / STPB, STPB>>>(out, ay, by, cy);

    // Z: lines = b*c*h*w = 221184 / 128 = 1728 blocks
    const int lines_z = BDIM * CDIM * HDIM * WDIM;
    solve_z_kernel<<<lines_z / STPB, STPB>>>(out, az, bz, cz);
}